// round 11
// baseline (speedup 1.0000x reference)
#include <cuda_runtime.h>
#include <cstdint>
#include <math.h>

// NaiveFourierKANLayer via warp-level fp16 mma.sync, single term, warp-specialized,
// R11: 3-buffer ring with named-barrier semaphores (producers run ahead) +
//      fragment software pipelining (LDSM(kk+1) issued under MMA(kk)).

#define NI 256
#define NG 300
#define NO 256
#define SPLITK 8
#define IPC (NI/SPLITK)      // 32 i per CTA
#define NGC 10               // 32-g chunks per i (chunk 9 zero-padded)
#define NSTAGE (IPC*NGC)     // 320

#define RSB 144              // smem row pitch bytes -> conflict-free ldmatrix
#define A_HI 0
#define B_HI 18432
#define STAGE_BYTES 36864
#define NBUF 3
#define DYN_SMEM (NBUF*STAGE_BYTES)   // 110592

#define BSCALE 2048.0f
#define FSCALE (1.0f/2048.0f)

__device__ float g_scratch[SPLITK * 1024 * 256];   // 8 MB split-K partials

// ---------------- helpers ----------------
__device__ __forceinline__ uint32_t smem_u32(const void* p) {
    uint32_t a;
    asm("{ .reg .u64 t; cvta.to.shared.u64 t, %1; cvt.u32.u64 %0, t; }" : "=r"(a) : "l"(p));
    return a;
}
// packf16(a,b): low f16 = a (even k), high f16 = b (odd k)
__device__ __forceinline__ uint32_t packf16(float a, float b) {
    uint32_t r;
    asm("cvt.rn.f16x2.f32 %0, %2, %1;" : "=r"(r) : "f"(a), "f"(b));
    return r;
}
__device__ __forceinline__ void rotstep(float& c, float& s, float cr, float sr) {
    float nc = fmaf(c, cr, -(s * sr));
    float ns = fmaf(s, cr, c * sr);
    c = nc; s = ns;
}

// named-barrier semaphores: full[b] = id 1+b, empty[b] = id 4+b, 512 arrivals
#define BAR_SYNC(id)   asm volatile("bar.sync %0, 512;"   :: "r"(id) : "memory")
#define BAR_ARRIVE(id) asm volatile("bar.arrive %0, 512;" :: "r"(id) : "memory")

#define LDSM4(r0,r1,r2,r3,addr)                                                  \
    asm volatile("ldmatrix.sync.aligned.m8n8.x4.shared.b16 {%0,%1,%2,%3}, [%4];" \
        : "=r"(r0), "=r"(r1), "=r"(r2), "=r"(r3) : "r"(addr))

#define MMA(d,a,b0,b1)                                                        \
    asm volatile("mma.sync.aligned.m16n8k16.row.col.f32.f16.f16.f32 "         \
        "{%0,%1,%2,%3},{%4,%5,%6,%7},{%8,%9},{%0,%1,%2,%3};"                  \
        : "+f"((d)[0]), "+f"((d)[1]), "+f"((d)[2]), "+f"((d)[3])              \
        : "r"((a)[0]), "r"((a)[1]), "r"((a)[2]), "r"((a)[3]), "r"(b0), "r"(b1))

// load one kk's fragments into slot s
#define LOAD_FRAGS(s, kkv)                                                     \
    do {                                                                       \
        LDSM4(bh[s][0], bh[s][1], bh[s][2], bh[s][3], pB + (kkv)*32);          \
        LDSM4(bh[s][4], bh[s][5], bh[s][6], bh[s][7], pB + 16*RSB + (kkv)*32); \
        LDSM4(ah[s][0][0], ah[s][0][1], ah[s][0][2], ah[s][0][3], pA + (kkv)*32);            \
        LDSM4(ah[s][1][0], ah[s][1][1], ah[s][1][2], ah[s][1][3], pA + 16*RSB + (kkv)*32);   \
        LDSM4(ah[s][2][0], ah[s][2][1], ah[s][2][2], ah[s][2][3], pA + 32*RSB + (kkv)*32);   \
        LDSM4(ah[s][3][0], ah[s][3][1], ah[s][3][2], ah[s][3][3], pA + 48*RSB + (kkv)*32);   \
    } while (0)

#define DO_MMAS(s)                                                             \
    do {                                                                       \
        _Pragma("unroll")                                                      \
        for (int mf = 0; mf < 4; ++mf) {                                       \
            _Pragma("unroll")                                                  \
            for (int f = 0; f < 4; ++f) {                                      \
                const int bi = (f >> 1)*4 + (f & 1)*2;                         \
                MMA(acc[mf][f], ah[s][mf], bh[s][bi], bh[s][bi+1]);            \
            }                                                                  \
        }                                                                      \
    } while (0)

extern __shared__ char dsmem[];

__global__ void __launch_bounds__(512, 1)
fkan_hmma(const float* __restrict__ x, const float* __restrict__ fc)
{
    const int tid  = threadIdx.x;
    const int lane = tid & 31;
    const int w    = tid >> 5;            // 0..15
    const int ks = blockIdx.x;            // split-K slice (i block)
    const int m0 = blockIdx.y * 128;      // batch-row tile
    const int n0 = blockIdx.z * 128;      // output-col tile

    const uint32_t smb = smem_u32(dsmem);

    if (w < 8) {
        // ================= PRODUCER (256 threads) =================
        const int rr = tid >> 1, q = tid & 1;        // A: row, g-half of 16
        const int bt = tid >> 7, bj = tid & 127;     // B: trig, j-row

        const float* xcol  = x + (size_t)(m0 + rr) * NI + ks * IPC;
        const float* bbase = fc + ((size_t)(bt * NO + n0 + bj) * NI + ks * IPC) * NG;

        float4 bf[8];
        #pragma unroll
        for (int q4 = 0; q4 < 8; ++q4) bf[q4] = *(const float4*)(bbase + q4 * 4);

        float c1 = 0.f, s1 = 0.f, c2 = 0.f, s2 = 0.f, c16 = 0.f, s16 = 0.f;
        float cc = 0.f, ss = 0.f;
        int pii = 0, pgc = 0, pb = 0;

        for (int ps = 0; ps < NSTAGE; ++ps) {
            if (pgc == 0) {
                const float t = xcol[pii];
                sincosf(t, &s1, &c1);
                c2 = fmaf(c1, c1, -(s1*s1)); s2 = 2.f*c1*s1;
                const float c4 = fmaf(c2, c2, -(s2*s2)), s4 = 2.f*c2*s2;
                const float c8 = fmaf(c4, c4, -(s4*s4)), s8 = 2.f*c4*s4;
                c16 = fmaf(c8, c8, -(s8*s8)); s16 = 2.f*c8*s8;
                cc = c1; ss = s1;                       // angle 1t
                if (q) rotstep(cc, ss, c16, s16);       // angle 17t
            }
            if (ps >= NBUF) BAR_SYNC(4 + pb);           // wait buffer free
            char* sm = dsmem + pb * STAGE_BYTES;

            // ---- A: 8 adjacent-g pairs; cos at k=gl, sin at k=32+gl ----
            #pragma unroll
            for (int m = 0; m < 8; ++m) {
                const int gl = q*16 + 2*m;
                const int gg = pgc*32 + gl;             // harmonic gg+1
                float ce = cc, se = ss;
                float co = fmaf(cc, c1, -(ss*s1));
                float so = fmaf(ss, c1,  cc*s1);
                if (gg     >= NG) { ce = 0.f; se = 0.f; }
                if (gg + 1 >= NG) { co = 0.f; so = 0.f; }
                const uint32_t offc = (uint32_t)rr * RSB + (uint32_t)gl * 2;
                *(uint32_t*)(sm + A_HI + offc)      = packf16(ce, co);
                *(uint32_t*)(sm + A_HI + offc + 64) = packf16(se, so);
                rotstep(cc, ss, c2, s2);                // +2t
            }
            rotstep(cc, ss, c16, s16);                  // +16t -> next chunk

            // ---- B: STS 16 u32 from prefetched regs (x2048, fp16) ----
            {
                const float* bv = (const float*)bf;
                #pragma unroll
                for (int pp = 0; pp < 16; ++pp) {
                    const uint32_t hp = packf16(bv[2*pp] * BSCALE, bv[2*pp+1] * BSCALE);
                    const uint32_t off = (uint32_t)bj * RSB + (uint32_t)(bt*32 + 2*pp) * 2;
                    *(uint32_t*)(sm + B_HI + off) = hp;
                }
            }
            BAR_ARRIVE(1 + pb);                         // publish buffer

            // advance counters, prefetch next stage's B
            if (++pgc == NGC) { pgc = 0; ++pii; }
            if (++pb == NBUF) pb = 0;
            if (ps + 1 < NSTAGE) {
                const float* p = bbase + (size_t)pii * NG + pgc * 32;
                #pragma unroll
                for (int q4 = 0; q4 < 8; ++q4) {
                    const int gg = pgc*32 + q4*4;
                    bf[q4] = (gg + 3 < NG) ? *(const float4*)(p + q4*4)
                                           : make_float4(0.f, 0.f, 0.f, 0.f);
                }
            }
        }
    } else {
        // ============ CONSUMER (8 warps, 2M x 4N, warp tile 64x32) ============
        const int wc = w - 8;
        const int wm = wc & 1, wn = wc >> 1;
        const uint32_t aoff = (uint32_t)(wm*64 + (lane & 7) + ((lane >> 3) & 1)*8) * RSB
                            + (uint32_t)(lane >> 4) * 16;
        const uint32_t boff = (uint32_t)(wn*32 + (lane & 7) + (lane >> 4)*8) * RSB
                            + (uint32_t)((lane >> 3) & 1) * 16;

        float acc[4][4][4];
        #pragma unroll
        for (int a = 0; a < 4; ++a)
            #pragma unroll
            for (int b = 0; b < 4; ++b)
                #pragma unroll
                for (int c = 0; c < 4; ++c) acc[a][b][c] = 0.f;

        int cb = 0, cgc = 0;
        for (int it = 0; it < NSTAGE; ++it) {
            BAR_SYNC(1 + cb);                           // stage is full
            const uint32_t base = smb + (uint32_t)cb * STAGE_BYTES;
            const uint32_t pA = base + aoff;
            const uint32_t pB = base + B_HI + boff;

            if (cgc != 9) {
                // pipelined: LDSM(kk+1) issued before MMAs(kk)
                uint32_t bh[2][8], ah[2][4][4];
                LOAD_FRAGS(0, 0);
                LOAD_FRAGS(1, 1);
                DO_MMAS(0);
                LOAD_FRAGS(0, 2);
                DO_MMAS(1);
                LOAD_FRAGS(1, 3);
                DO_MMAS(0);
                DO_MMAS(1);
            } else {
                // padded chunk: only kk=0 and kk=2 carry real data
                uint32_t bh[2][8], ah[2][4][4];
                LOAD_FRAGS(0, 0);
                LOAD_FRAGS(1, 2);
                DO_MMAS(0);
                DO_MMAS(1);
            }
            BAR_ARRIVE(4 + cb);                         // buffer free
            if (++cb == NBUF) cb = 0;
            if (++cgc == NGC) cgc = 0;
        }

        // ---- epilogue: accumulators (x2048) -> split-K scratch ----
        float* dst = g_scratch + ((size_t)ks << 18);
        #pragma unroll
        for (int mf = 0; mf < 4; ++mf) {
            const int r = m0 + wm*64 + mf*16 + (lane >> 2);
            #pragma unroll
            for (int f = 0; f < 4; ++f) {
                const int c = n0 + wn*32 + f*8 + (lane & 3)*2;
                float2 v0, v1;
                v0.x = acc[mf][f][0] * FSCALE; v0.y = acc[mf][f][1] * FSCALE;
                v1.x = acc[mf][f][2] * FSCALE; v1.y = acc[mf][f][3] * FSCALE;
                *(float2*)(dst + (size_t)r * NO + c)       = v0;
                *(float2*)(dst + (size_t)(r + 8) * NO + c) = v1;
            }
        }
    }
}

__global__ void __launch_bounds__(512, 1)
fkan_reduce(const float* __restrict__ bias, float* __restrict__ out)
{
    const int idx = blockIdx.x * 512 + threadIdx.x;
    float a = bias[idx & 255];
    #pragma unroll
    for (int k = 0; k < SPLITK; ++k)
        a += g_scratch[((size_t)k << 18) + idx];
    out[idx] = a;
}

extern "C" void kernel_launch(void* const* d_in, const int* in_sizes, int n_in,
                              void* d_out, int out_size) {
    const float* x    = (const float*)d_in[0];
    const float* fc   = (const float*)d_in[1];
    const float* bias = (const float*)d_in[2];
    float* out        = (float*)d_out;

    cudaFuncSetAttribute(fkan_hmma, cudaFuncAttributeMaxDynamicSharedMemorySize, DYN_SMEM);
    fkan_hmma<<<dim3(SPLITK, 8, 2), 512, DYN_SMEM>>>(x, fc);
    fkan_reduce<<<512, 512>>>(bias, out);
}

// round 12
// speedup vs baseline: 1.1729x; 1.1729x over previous
#include <cuda_runtime.h>
#include <cstdint>
#include <math.h>

// NaiveFourierKANLayer, fp16 mma.sync single term, R12:
//  - CTA tile 128x256 (N full), 8 warps, 64x64 warp tiles -> 128 MMA/warp/stage
//    (long MMA runs; R4 showed the SIMT HMMA pipe hits 14 cyc/instr this way)
//  - B pre-converted to fp16 (x2048) in smem-row layout -> cp.async fill
//  - A = cos/sin rotation recurrence -> fp16 STS
//  - split-K 16 over i, fp32 scratch + reduce

#define NI 256
#define NG 300
#define NO 256
#define SPLITK 16
#define IPC (NI/SPLITK)      // 16 i per CTA
#define NGC 10               // 32-g chunks per i (chunk 9 zero-padded)
#define NSTAGE (IPC*NGC)     // 160

#define RSB 144              // smem row pitch bytes -> conflict-free ldmatrix
#define A_OFF 0
#define B_OFF 18432          // after 128 A rows
#define STAGE_BYTES 55296    // 18432 + 256*144
#define DYN_SMEM (2*STAGE_BYTES)   // 110592

#define BSCALE 2048.0f
#define FSCALE (1.0f/2048.0f)

__device__ float    g_scratch[SPLITK * 1024 * 256];     // 16 MB split-K partials
__device__ uint32_t g_Bh[256u * 256u * 10u * 32u];      // 83.9 MB fp16 B, smem-row layout
// layout: [j][i][gc][32 u32]  (row = 64 fp16 k-values: k0..31 = W0*cos-slot, 32..63 = W1*sin-slot)

// ---------------- helpers ----------------
__device__ __forceinline__ uint32_t smem_u32(const void* p) {
    uint32_t a;
    asm("{ .reg .u64 t; cvta.to.shared.u64 t, %1; cvt.u32.u64 %0, t; }" : "=r"(a) : "l"(p));
    return a;
}
// packf16(a,b): low f16 = a (even k), high f16 = b (odd k)
__device__ __forceinline__ uint32_t packf16(float a, float b) {
    uint32_t r;
    asm("cvt.rn.f16x2.f32 %0, %2, %1;" : "=r"(r) : "f"(a), "f"(b));
    return r;
}
__device__ __forceinline__ void rotstep(float& c, float& s, float cr, float sr) {
    float nc = fmaf(c, cr, -(s * sr));
    float ns = fmaf(s, cr, c * sr);
    c = nc; s = ns;
}

#define LDSM4(r0,r1,r2,r3,addr)                                                  \
    asm volatile("ldmatrix.sync.aligned.m8n8.x4.shared.b16 {%0,%1,%2,%3}, [%4];" \
        : "=r"(r0), "=r"(r1), "=r"(r2), "=r"(r3) : "r"(addr))

#define MMA(d,a,b0,b1)                                                        \
    asm volatile("mma.sync.aligned.m16n8k16.row.col.f32.f16.f16.f32 "         \
        "{%0,%1,%2,%3},{%4,%5,%6,%7},{%8,%9},{%0,%1,%2,%3};"                  \
        : "+f"((d)[0]), "+f"((d)[1]), "+f"((d)[2]), "+f"((d)[3])              \
        : "r"((a)[0]), "r"((a)[1]), "r"((a)[2]), "r"((a)[3]), "r"(b0), "r"(b1))

#define CP16(dst,src) \
    asm volatile("cp.async.cg.shared.global [%0], [%1], 16;" :: "r"(dst), "l"(src))
#define CP_COMMIT() asm volatile("cp.async.commit_group;" ::: "memory")
#define CP_WAIT0()  asm volatile("cp.async.wait_group 0;" ::: "memory")

extern __shared__ char dsmem[];

// ---------------- B pre-conversion: fc fp32 -> fp16 (x2048), smem-row layout ----------------
__global__ void __launch_bounds__(512, 2)
fkan_conv(const float* __restrict__ fc)
{
    const int idx = blockIdx.x * 512 + threadIdx.x;     // 20,971,520
    const int kk2 = idx & 31;                           // u32 within 64-k row
    const int t   = idx >> 5;
    const int gc  = t % NGC;
    const int i   = (t / NGC) & 255;
    const int j   = t / (NGC * 256);

    const int bt = kk2 >> 4;                            // 0 = W0/cos slot, 1 = W1/sin slot
    const int g0 = gc * 32 + (kk2 & 15) * 2;            // g index (harmonic g0+1)
    const float* src = fc + ((size_t)(bt * NO + j) * NI + i) * NG;
    const float v0 = (g0     < NG) ? src[g0]     * BSCALE : 0.f;
    const float v1 = (g0 + 1 < NG) ? src[g0 + 1] * BSCALE : 0.f;
    g_Bh[idx] = packf16(v0, v1);
}

// ---------------- main MMA kernel ----------------
__global__ void __launch_bounds__(256, 1)
fkan_hmma(const float* __restrict__ x)
{
    const int tid  = threadIdx.x;
    const int lane = tid & 31;
    const int w    = tid >> 5;            // 0..7
    const int ks = blockIdx.x;            // split-K slice (i block)
    const int m0 = blockIdx.y * 128;      // batch-row tile

    const uint32_t smb = smem_u32(dsmem);

    // ---- producer maps ----
    const int rr = tid >> 1, q = tid & 1;               // A: row, g-half of 16
    // B: thread j = tid, 8 x 16B cp.async per stage; src advances +32 u32/stage
    const uint32_t* bsrc = g_Bh + (((uint32_t)tid * 256u + (uint32_t)(ks * IPC)) * 10u) * 32u;
    const uint32_t  bdst = (uint32_t)B_OFF + (uint32_t)tid * RSB;

    // ---- mma maps: 8 warps = 2(M) x 4(N), warp tile 64x64 ----
    const int wm = w & 1, wn = w >> 1;
    const uint32_t aoff = (uint32_t)(wm*64 + (lane & 7) + ((lane >> 3) & 1)*8) * RSB
                        + (uint32_t)(lane >> 4) * 16;
    const uint32_t boff = (uint32_t)(wn*64 + (lane & 7) + (lane >> 4)*8) * RSB
                        + (uint32_t)((lane >> 3) & 1) * 16;

    float acc[4][8][4];
    #pragma unroll
    for (int a = 0; a < 4; ++a)
        #pragma unroll
        for (int b = 0; b < 8; ++b)
            #pragma unroll
            for (int c = 0; c < 4; ++c) acc[a][b][c] = 0.f;

    const float* xcol = x + (size_t)(m0 + rr) * NI + ks * IPC;

    // prologue: B cp.async for stage 0
    {
        const uint32_t d0 = smb + bdst;
        #pragma unroll
        for (int c = 0; c < 8; ++c) CP16(d0 + c * 16, bsrc + c * 4);
        CP_COMMIT();
    }

    int it = 0;
    for (int ii = 0; ii < IPC; ++ii) {
        const float t = xcol[ii];
        float s1, c1;
        sincosf(t, &s1, &c1);
        const float c2 = fmaf(c1, c1, -(s1*s1)), s2 = 2.f*c1*s1;
        const float c4 = fmaf(c2, c2, -(s2*s2)), s4 = 2.f*c2*s2;
        const float c8 = fmaf(c4, c4, -(s4*s4)), s8 = 2.f*c4*s4;
        const float c16 = fmaf(c8, c8, -(s8*s8)), s16 = 2.f*c8*s8;
        float cc = c1, ss = s1;                     // angle 1t
        if (q) rotstep(cc, ss, c16, s16);           // angle 17t

        for (int gc = 0; gc < NGC; ++gc, ++it) {
            const uint32_t stg = (uint32_t)(it & 1) * STAGE_BYTES;
            char* sm = dsmem + stg;

            // ---- A: 8 adjacent-g pairs; cos at k=gl, sin at k=32+gl ----
            #pragma unroll
            for (int m = 0; m < 8; ++m) {
                const int gl = q*16 + 2*m;
                const int gg = gc*32 + gl;          // harmonic gg+1
                float ce = cc, se = ss;
                float co = fmaf(cc, c1, -(ss*s1));
                float so = fmaf(ss, c1,  cc*s1);
                if (gg     >= NG) { ce = 0.f; se = 0.f; }
                if (gg + 1 >= NG) { co = 0.f; so = 0.f; }
                const uint32_t offc = (uint32_t)rr * RSB + (uint32_t)gl * 2;
                *(uint32_t*)(sm + A_OFF + offc)      = packf16(ce, co);
                *(uint32_t*)(sm + A_OFF + offc + 64) = packf16(se, so);
                rotstep(cc, ss, c2, s2);            // +2t
            }
            rotstep(cc, ss, c16, s16);              // +16t -> next 32-g chunk

            CP_WAIT0();                 // B(it) landed
            __syncthreads();            // A(it) visible; MMA(it-1) complete

            // ---- issue B cp.async for stage it+1 (src is linear +32 u32) ----
            if (it + 1 < NSTAGE) {
                const uint32_t* src = bsrc + (uint32_t)(it + 1) * 32u;
                const uint32_t d0 = smb + (uint32_t)(((it + 1) & 1) * STAGE_BYTES) + bdst;
                #pragma unroll
                for (int c = 0; c < 8; ++c) CP16(d0 + c * 16, src + c * 4);
                CP_COMMIT();
            }

            // ---- consume: 4 K-steps x (4 mf x 8 f) ----
            const uint32_t pA = smb + stg + aoff;
            const uint32_t pB = smb + stg + B_OFF + boff;
            const int kkstep = (gc == 9) ? 2 : 1;   // padded sub-steps skipped
            #pragma unroll 4
            for (int kk = 0; kk < 4; kk += kkstep) {
                uint32_t bh[16];
                #pragma unroll
                for (int p = 0; p < 4; ++p)
                    LDSM4(bh[4*p], bh[4*p+1], bh[4*p+2], bh[4*p+3],
                          pB + p*(16*RSB) + kk*32);
                uint32_t ah[4][4];
                #pragma unroll
                for (int mf = 0; mf < 4; ++mf)
                    LDSM4(ah[mf][0], ah[mf][1], ah[mf][2], ah[mf][3],
                          pA + mf*(16*RSB) + kk*32);
                #pragma unroll
                for (int mf = 0; mf < 4; ++mf)
                    #pragma unroll
                    for (int f = 0; f < 8; ++f)
                        MMA(acc[mf][f], ah[mf], bh[2*f], bh[2*f+1]);
            }
        }
    }

    // ---- epilogue: accumulators (x2048) -> split-K scratch ----
    float* dst = g_scratch + ((size_t)ks << 18);
    #pragma unroll
    for (int mf = 0; mf < 4; ++mf) {
        const int r = m0 + wm*64 + mf*16 + (lane >> 2);
        #pragma unroll
        for (int f = 0; f < 8; ++f) {
            const int c = wn*64 + f*8 + (lane & 3)*2;
            float2 v0, v1;
            v0.x = acc[mf][f][0] * FSCALE; v0.y = acc[mf][f][1] * FSCALE;
            v1.x = acc[mf][f][2] * FSCALE; v1.y = acc[mf][f][3] * FSCALE;
            *(float2*)(dst + (size_t)r * NO + c)       = v0;
            *(float2*)(dst + (size_t)(r + 8) * NO + c) = v1;
        }
    }
}

__global__ void __launch_bounds__(512, 1)
fkan_reduce(const float* __restrict__ bias, float* __restrict__ out)
{
    const int idx = blockIdx.x * 512 + threadIdx.x;
    float a = bias[idx & 255];
    #pragma unroll
    for (int k = 0; k < SPLITK; ++k)
        a += g_scratch[((size_t)k << 18) + idx];
    out[idx] = a;
}

extern "C" void kernel_launch(void* const* d_in, const int* in_sizes, int n_in,
                              void* d_out, int out_size) {
    const float* x    = (const float*)d_in[0];
    const float* fc   = (const float*)d_in[1];
    const float* bias = (const float*)d_in[2];
    float* out        = (float*)d_out;

    cudaFuncSetAttribute(fkan_hmma, cudaFuncAttributeMaxDynamicSharedMemorySize, DYN_SMEM);
    fkan_conv<<<40960, 512>>>(fc);
    fkan_hmma<<<dim3(SPLITK, 8), 256, DYN_SMEM>>>(x);
    fkan_reduce<<<512, 512>>>(bias, out);
}

// round 13
// speedup vs baseline: 1.3158x; 1.1218x over previous
#include <cuda_runtime.h>
#include <cstdint>
#include <math.h>

// NaiveFourierKANLayer, fp16 mma.sync single term, R13:
//  - CTA tile 128x256, 8 warps, 64x64 warp tiles (17.3 cyc/HMMA measured in R12)
//  - produce(it+1) interleaved INSIDE consume(it): A-gen FMAs/STS issue in the
//    gaps of the 128-MMA run instead of serially before the barrier
//  - B pre-converted fp16 (x2048) via vectorized conv (4 u32/thread)
//  - split-K 16 over i, fp32 scratch + reduce

#define NI 256
#define NG 300
#define NO 256
#define SPLITK 16
#define IPC (NI/SPLITK)      // 16 i per CTA
#define NGC 10               // 32-g chunks per i (chunk 9 zero-padded)
#define NSTAGE (IPC*NGC)     // 160

#define RSB 144
#define A_OFF 0
#define B_OFF 18432
#define STAGE_BYTES 55296
#define DYN_SMEM (2*STAGE_BYTES)

#define BSCALE 2048.0f
#define FSCALE (1.0f/2048.0f)

__device__ float    g_scratch[SPLITK * 1024 * 256];     // 16 MB
__device__ uint32_t g_Bh[256u * 256u * 10u * 32u];      // 83.9 MB fp16 B, smem-row layout

// ---------------- helpers ----------------
__device__ __forceinline__ uint32_t smem_u32(const void* p) {
    uint32_t a;
    asm("{ .reg .u64 t; cvta.to.shared.u64 t, %1; cvt.u32.u64 %0, t; }" : "=r"(a) : "l"(p));
    return a;
}
__device__ __forceinline__ uint32_t packf16(float a, float b) {
    uint32_t r;
    asm("cvt.rn.f16x2.f32 %0, %2, %1;" : "=r"(r) : "f"(a), "f"(b));
    return r;
}
__device__ __forceinline__ void rotstep(float& c, float& s, float cr, float sr) {
    float nc = fmaf(c, cr, -(s * sr));
    float ns = fmaf(s, cr, c * sr);
    c = nc; s = ns;
}

#define LDSM4(r0,r1,r2,r3,addr)                                                  \
    asm volatile("ldmatrix.sync.aligned.m8n8.x4.shared.b16 {%0,%1,%2,%3}, [%4];" \
        : "=r"(r0), "=r"(r1), "=r"(r2), "=r"(r3) : "r"(addr))

#define MMA(d,a,b0,b1)                                                        \
    asm volatile("mma.sync.aligned.m16n8k16.row.col.f32.f16.f16.f32 "         \
        "{%0,%1,%2,%3},{%4,%5,%6,%7},{%8,%9},{%0,%1,%2,%3};"                  \
        : "+f"((d)[0]), "+f"((d)[1]), "+f"((d)[2]), "+f"((d)[3])              \
        : "r"((a)[0]), "r"((a)[1]), "r"((a)[2]), "r"((a)[3]), "r"(b0), "r"(b1))

#define CP16(dst,src) \
    asm volatile("cp.async.cg.shared.global [%0], [%1], 16;" :: "r"(dst), "l"(src))
#define CP_COMMIT() asm volatile("cp.async.commit_group;" ::: "memory")
#define CP_WAIT0()  asm volatile("cp.async.wait_group 0;" ::: "memory")

extern __shared__ char dsmem[];

// ---------------- B pre-conversion (vectorized: 4 u32 / thread) ----------------
__global__ void __launch_bounds__(512, 2)
fkan_conv(const float* __restrict__ fc)
{
    const int idx = blockIdx.x * 512 + threadIdx.x;     // 5,242,880 threads
    const int u4  = idx & 7;                            // quad-of-4-u32 within 32-u32 row
    const int t   = idx >> 3;
    const int gc  = t % NGC;
    const int i   = (t / NGC) & 255;
    const int j   = t / (NGC * 256);

    const int bt = u4 >> 2;                             // 0=W0/cos slot, 1=W1/sin slot
    const int g0 = gc * 32 + (u4 & 3) * 8;              // 8 g values
    const float* src = fc + ((size_t)(bt * NO + j) * NI + i) * NG + g0;

    float4 f0 = (g0 + 3 < NG) ? *(const float4*)(src)
                              : make_float4(0.f, 0.f, 0.f, 0.f);
    float4 f1 = (g0 + 7 < NG) ? *(const float4*)(src + 4)
                              : make_float4(0.f, 0.f, 0.f, 0.f);
    uint4 o;
    o.x = packf16(f0.x * BSCALE, f0.y * BSCALE);
    o.y = packf16(f0.z * BSCALE, f0.w * BSCALE);
    o.z = packf16(f1.x * BSCALE, f1.y * BSCALE);
    o.w = packf16(f1.z * BSCALE, f1.w * BSCALE);
    *(uint4*)(g_Bh + (size_t)idx * 4) = o;
}

// ---------------- main MMA kernel ----------------
__global__ void __launch_bounds__(256, 1)
fkan_hmma(const float* __restrict__ x)
{
    const int tid  = threadIdx.x;
    const int lane = tid & 31;
    const int w    = tid >> 5;
    const int ks = blockIdx.x;
    const int m0 = blockIdx.y * 128;

    const uint32_t smb = smem_u32(dsmem);

    // producer maps
    const int rr = tid >> 1, q = tid & 1;               // A: row, g-half of 16
    const uint32_t* bsrc = g_Bh + (((uint32_t)tid * 256u + (uint32_t)(ks * IPC)) * 10u) * 32u;
    const uint32_t  bdst = (uint32_t)B_OFF + (uint32_t)tid * RSB;

    // mma maps: 8 warps = 2(M) x 4(N), warp tile 64x64
    const int wm = w & 1, wn = w >> 1;
    const uint32_t aoff = (uint32_t)(wm*64 + (lane & 7) + ((lane >> 3) & 1)*8) * RSB
                        + (uint32_t)(lane >> 4) * 16;
    const uint32_t boff = (uint32_t)(wn*64 + (lane & 7) + (lane >> 4)*8) * RSB
                        + (uint32_t)((lane >> 3) & 1) * 16;

    float acc[4][8][4];
    #pragma unroll
    for (int a = 0; a < 4; ++a)
        #pragma unroll
        for (int b = 0; b < 8; ++b)
            #pragma unroll
            for (int c = 0; c < 4; ++c) acc[a][b][c] = 0.f;

    const float* xcol = x + (size_t)(m0 + rr) * NI + ks * IPC;

    // ---- rotation / production state (for NEXT stage to be produced) ----
    float c1, s1, c2, s2, c16, s16, cc, ss;
    int png = 0, pni = 0;                               // next-produce gc, i-index

    // setup rotation for i-index ii
    #define SETUP_I(ii) do {                                                   \
        const float t_ = xcol[ii];                                             \
        sincosf(t_, &s1, &c1);                                                 \
        c2 = fmaf(c1, c1, -(s1*s1)); s2 = 2.f*c1*s1;                           \
        const float c4_ = fmaf(c2, c2, -(s2*s2)), s4_ = 2.f*c2*s2;             \
        const float c8_ = fmaf(c4_, c4_, -(s4_*s4_)), s8_ = 2.f*c4_*s4_;       \
        c16 = fmaf(c8_, c8_, -(s8_*s8_)); s16 = 2.f*c8_*s8_;                   \
        cc = c1; ss = s1;                                                      \
        if (q) rotstep(cc, ss, c16, s16);                                      \
    } while (0)

    // produce adjacent pair m (g = png*32 + q*16 + 2m, 2m+1) into smn
    #define GEN_PAIR(smn, m) do {                                              \
        const int gl_ = q*16 + 2*(m);                                          \
        const int gg_ = png*32 + gl_;                                          \
        float ce_ = cc, se_ = ss;                                              \
        float co_ = fmaf(cc, c1, -(ss*s1));                                    \
        float so_ = fmaf(ss, c1,  cc*s1);                                      \
        if (gg_     >= NG) { ce_ = 0.f; se_ = 0.f; }                           \
        if (gg_ + 1 >= NG) { co_ = 0.f; so_ = 0.f; }                           \
        const uint32_t offc_ = (uint32_t)rr * RSB + (uint32_t)gl_ * 2;         \
        *(uint32_t*)((smn) + A_OFF + offc_)      = packf16(ce_, co_);          \
        *(uint32_t*)((smn) + A_OFF + offc_ + 64) = packf16(se_, so_);          \
        rotstep(cc, ss, c2, s2);                                               \
    } while (0)

    #define END_CHUNK() do {                                                   \
        rotstep(cc, ss, c16, s16);                                             \
        if (++png == NGC) { png = 0; ++pni; }                                  \
    } while (0)

    #define CONSUME_KK(kk) do {                                                \
        uint32_t bh[16];                                                       \
        _Pragma("unroll")                                                      \
        for (int p = 0; p < 4; ++p)                                            \
            LDSM4(bh[4*p], bh[4*p+1], bh[4*p+2], bh[4*p+3],                    \
                  pB + p*(16*RSB) + (kk)*32);                                  \
        uint32_t ah[4][4];                                                     \
        _Pragma("unroll")                                                      \
        for (int mf = 0; mf < 4; ++mf)                                         \
            LDSM4(ah[mf][0], ah[mf][1], ah[mf][2], ah[mf][3],                  \
                  pA + mf*(16*RSB) + (kk)*32);                                 \
        _Pragma("unroll")                                                      \
        for (int mf = 0; mf < 4; ++mf)                                         \
            _Pragma("unroll")                                                  \
            for (int f = 0; f < 8; ++f)                                        \
                MMA(acc[mf][f], ah[mf], bh[2*f], bh[2*f+1]);                   \
    } while (0)

    // ---- prologue: produce stage 0, issue cp(0) ----
    SETUP_I(0);
    {
        char* sm0 = dsmem;
        #pragma unroll
        for (int m = 0; m < 8; ++m) GEN_PAIR(sm0, m);
        END_CHUNK();
        const uint32_t d0 = smb + bdst;
        #pragma unroll
        for (int c = 0; c < 8; ++c) CP16(d0 + c * 16, bsrc + c * 4);
        CP_COMMIT();
    }

    int cgc = 0;
    for (int it = 0; it < NSTAGE; ++it) {
        CP_WAIT0();
        __syncthreads();                    // stage it fully visible

        const bool dp = (it + 1 < NSTAGE);
        char* smn = dsmem + ((it + 1) & 1) * STAGE_BYTES;

        // issue B cp.async for stage it+1
        if (dp) {
            const uint32_t* src = bsrc + (uint32_t)(it + 1) * 32u;
            const uint32_t d0 = smb + (uint32_t)(((it + 1) & 1) * STAGE_BYTES) + bdst;
            #pragma unroll
            for (int c = 0; c < 8; ++c) CP16(d0 + c * 16, src + c * 4);
            CP_COMMIT();
        }

        const uint32_t stg = (uint32_t)(it & 1) * STAGE_BYTES;
        const uint32_t pA = smb + stg + aoff;
        const uint32_t pB = smb + stg + B_OFF + boff;

        if (cgc != 9) {
            CONSUME_KK(0);
            if (dp) { if (png == 0) SETUP_I(pni); GEN_PAIR(smn, 0); GEN_PAIR(smn, 1); }
            CONSUME_KK(1);
            if (dp) { GEN_PAIR(smn, 2); GEN_PAIR(smn, 3); }
            CONSUME_KK(2);
            if (dp) { GEN_PAIR(smn, 4); GEN_PAIR(smn, 5); }
            CONSUME_KK(3);
            if (dp) { GEN_PAIR(smn, 6); GEN_PAIR(smn, 7); END_CHUNK(); }
        } else {
            CONSUME_KK(0);
            if (dp) {
                if (png == 0) SETUP_I(pni);
                GEN_PAIR(smn, 0); GEN_PAIR(smn, 1);
                GEN_PAIR(smn, 2); GEN_PAIR(smn, 3);
            }
            CONSUME_KK(2);
            if (dp) {
                GEN_PAIR(smn, 4); GEN_PAIR(smn, 5);
                GEN_PAIR(smn, 6); GEN_PAIR(smn, 7);
                END_CHUNK();
            }
        }
        if (++cgc == NGC) cgc = 0;
    }

    // ---- epilogue: accumulators (x2048) -> split-K scratch ----
    float* dst = g_scratch + ((size_t)ks << 18);
    #pragma unroll
    for (int mf = 0; mf < 4; ++mf) {
        const int r = m0 + wm*64 + mf*16 + (lane >> 2);
        #pragma unroll
        for (int f = 0; f < 8; ++f) {
            const int c = wn*64 + f*8 + (lane & 3)*2;
            float2 v0, v1;
            v0.x = acc[mf][f][0] * FSCALE; v0.y = acc[mf][f][1] * FSCALE;
            v1.x = acc[mf][f][2] * FSCALE; v1.y = acc[mf][f][3] * FSCALE;
            *(float2*)(dst + (size_t)r * NO + c)       = v0;
            *(float2*)(dst + (size_t)(r + 8) * NO + c) = v1;
        }
    }
}

__global__ void __launch_bounds__(512, 1)
fkan_reduce(const float* __restrict__ bias, float* __restrict__ out)
{
    const int idx = blockIdx.x * 512 + threadIdx.x;
    float a = bias[idx & 255];
    #pragma unroll
    for (int k = 0; k < SPLITK; ++k)
        a += g_scratch[((size_t)k << 18) + idx];
    out[idx] = a;
}

extern "C" void kernel_launch(void* const* d_in, const int* in_sizes, int n_in,
                              void* d_out, int out_size) {
    const float* x    = (const float*)d_in[0];
    const float* fc   = (const float*)d_in[1];
    const float* bias = (const float*)d_in[2];
    float* out        = (float*)d_out;

    cudaFuncSetAttribute(fkan_hmma, cudaFuncAttributeMaxDynamicSharedMemorySize, DYN_SMEM);
    fkan_conv<<<10240, 512>>>(fc);
    fkan_hmma<<<dim3(SPLITK, 8), 256, DYN_SMEM>>>(x);
    fkan_reduce<<<512, 512>>>(bias, out);
}